// round 5
// baseline (speedup 1.0000x reference)
#include <cuda_runtime.h>
#include <cstdint>

#define T_STEPS 48
#define B_SZ    512
#define D_SZ    1024
#define H_SZ    1024
#define G4      (4 * H_SZ)

// ---------------- scratch (static device globals; no allocation) ----------
__device__ float g_pooled[B_SZ * D_SZ];                       // 2 MB
__device__ float g_Gpool [B_SZ * G4];                         // 8 MB
__device__ float g_Gin   [(size_t)(T_STEPS - 1) * B_SZ * G4]; // ~386 MB
__device__ float g_h     [2][B_SZ * H_SZ];                    // 4 MB ping-pong
__device__ float g_c     [B_SZ * H_SZ];                       // 2 MB
__device__ float g_Wih_p [(size_t)G4 * 2 * D_SZ];             // 32 MB (gate-permuted)
__device__ float g_Whh_p [(size_t)G4 * H_SZ];                 // 16 MB (gate-permuted)
__device__ float g_bias_p[G4];                                // combined permuted bias

// ===================== helpers =============================================
__device__ __forceinline__ float tf32_round(float x) {
    float y; asm("cvt.rna.tf32.f32 %0, %1;" : "=f"(y) : "f"(x)); return y;
}
__device__ __forceinline__ float sigf(float x) {
    return 1.f / (1.f + __expf(-x));
}
__device__ __forceinline__ float tanh_fast(float x) {
    // safe: x->+inf => e=inf => 1 - 0 = 1; x->-inf => e=0 => -1
    float e = __expf(2.f * x);
    return 1.f - 2.f / (e + 1.f);
}

// mma.sync m16n8k8 tf32: D += A*B (row.col), fp32 accumulate
#define MMA_TF32(d, a, b)                                                     \
    asm volatile(                                                             \
        "mma.sync.aligned.m16n8k8.row.col.f32.tf32.tf32.f32 "                 \
        "{%0,%1,%2,%3}, {%4,%5,%6,%7}, {%8,%9}, {%0,%1,%2,%3};"               \
        : "+f"((d)[0]), "+f"((d)[1]), "+f"((d)[2]), "+f"((d)[3])              \
        : "r"((a)[0]), "r"((a)[1]), "r"((a)[2]), "r"((a)[3]),                 \
          "r"((b)[0]), "r"((b)[1]))

// ===================== tensor-core tf32 split-fp32 GEMM ====================
// C[M,N] = A[M,K] @ W[N,K]^T, tile 128x128, BK=32, 8 warps (2x4), 64x32 warp tile.
// Split: x = hi + lo; D += Ah*Bh + Ah*Bl + Al*Bh  (err ~2^-21).
// Double-buffered smem; stores for tile k+1 interleaved with MMAs of tile k.
// MODE 0: C = acc (+add[row(%add_mod)]) (+bias1) (+bias2)
// MODE 1: LSTM step epilogue: gates = acc + add (Gin, permuted gate-major cols);
//         computes h,c; writes hst, cst, outp[:, tstep, :]. C/bias unused.
#define BK       32
#define SSTRIDE  36   // floats; conflict-free frags; 16B aligned
#define TILE_F   (128 * SSTRIDE)
#define BUF_F    (4 * TILE_F)               // AsH, AsL, BsH, BsL
#define SMEM_B   (2 * BUF_F * 4)            // 147456 bytes

template<int MODE>
__global__ __launch_bounds__(256)
void gemm_mma(const float* __restrict__ A, int lda,
              const float* __restrict__ W, int ldw,
              const float* __restrict__ add, int add_mod,
              const float* __restrict__ bias1, const float* __restrict__ bias2,
              float* __restrict__ C, int N, int K,
              float* __restrict__ cst, float* __restrict__ hst,
              float* __restrict__ outp, int tstep)
{
    extern __shared__ float sm[];

    const int tid = threadIdx.x;
    const int wid = tid >> 5, lid = tid & 31;
    const int wm  = wid >> 2, wn = wid & 3;       // 2x4 warp grid
    const int g   = lid >> 2, t  = lid & 3;       // mma lane decomposition
    const int m0  = blockIdx.y * 128;
    const int n0  = blockIdx.x * 128;

    // loader mapping: 256 threads cover 128 rows x 8 float4 (32 cols)
    const int j  = tid & 7;
    const int r0 = tid >> 3;

    float acc[4][4][4];
    #pragma unroll
    for (int a_ = 0; a_ < 4; a_++)
        #pragma unroll
        for (int b_ = 0; b_ < 4; b_++)
            #pragma unroll
            for (int e = 0; e < 4; e++) acc[a_][b_][e] = 0.f;

    const float* Abase = A + (size_t)(m0 + r0) * lda + j * 4;
    const float* Wbase = W + (size_t)(n0 + r0) * ldw + j * 4;

    float4 pa[4], pw[4];

#define LOADG(ko)                                                             \
    do {                                                                      \
        _Pragma("unroll")                                                     \
        for (int rr = 0; rr < 4; rr++) {                                      \
            pa[rr] = *(const float4*)(Abase + (size_t)rr * 32 * lda + (ko));  \
            pw[rr] = *(const float4*)(Wbase + (size_t)rr * 32 * ldw + (ko));  \
        }                                                                     \
    } while (0)

#define STORE_RR(rr, buf)                                                     \
    do {                                                                      \
        float* AsH_ = sm + (buf) * BUF_F;                                     \
        float* AsL_ = AsH_ + TILE_F;                                          \
        float* BsH_ = AsH_ + 2 * TILE_F;                                      \
        float* BsL_ = AsH_ + 3 * TILE_F;                                      \
        const int r = r0 + (rr) * 32;                                         \
        float4 v = pa[rr], hi, lo;                                            \
        hi.x = tf32_round(v.x); lo.x = tf32_round(v.x - hi.x);                \
        hi.y = tf32_round(v.y); lo.y = tf32_round(v.y - hi.y);                \
        hi.z = tf32_round(v.z); lo.z = tf32_round(v.z - hi.z);                \
        hi.w = tf32_round(v.w); lo.w = tf32_round(v.w - hi.w);                \
        *(float4*)(AsH_ + r * SSTRIDE + j * 4) = hi;                          \
        *(float4*)(AsL_ + r * SSTRIDE + j * 4) = lo;                          \
        v = pw[rr];                                                           \
        hi.x = tf32_round(v.x); lo.x = tf32_round(v.x - hi.x);                \
        hi.y = tf32_round(v.y); lo.y = tf32_round(v.y - hi.y);                \
        hi.z = tf32_round(v.z); lo.z = tf32_round(v.z - hi.z);                \
        hi.w = tf32_round(v.w); lo.w = tf32_round(v.w - hi.w);                \
        *(float4*)(BsH_ + r * SSTRIDE + j * 4) = hi;                          \
        *(float4*)(BsL_ + r * SSTRIDE + j * 4) = lo;                          \
    } while (0)

#define MMA_KS(ks, buf)                                                       \
    do {                                                                      \
        const float* AsH_ = sm + (buf) * BUF_F;                               \
        const float* AsL_ = AsH_ + TILE_F;                                    \
        const float* BsH_ = AsH_ + 2 * TILE_F;                                \
        const float* BsL_ = AsH_ + 3 * TILE_F;                                \
        uint32_t ah[4][4], al[4][4], bh[4][2], bl[4][2];                      \
        _Pragma("unroll")                                                     \
        for (int mt = 0; mt < 4; mt++) {                                      \
            const float* p = AsH_ + (wm*64 + mt*16 + g) * SSTRIDE + (ks)*8 + t; \
            ah[mt][0] = __float_as_uint(p[0]);                                \
            ah[mt][1] = __float_as_uint(p[8 * SSTRIDE]);                      \
            ah[mt][2] = __float_as_uint(p[4]);                                \
            ah[mt][3] = __float_as_uint(p[8 * SSTRIDE + 4]);                  \
        }                                                                     \
        _Pragma("unroll")                                                     \
        for (int nt = 0; nt < 4; nt++) {                                      \
            const float* p = BsH_ + (wn*32 + nt*8 + g) * SSTRIDE + (ks)*8 + t;  \
            bh[nt][0] = __float_as_uint(p[0]);                                \
            bh[nt][1] = __float_as_uint(p[4]);                                \
        }                                                                     \
        _Pragma("unroll")                                                     \
        for (int mt = 0; mt < 4; mt++)                                        \
            _Pragma("unroll")                                                 \
            for (int nt = 0; nt < 4; nt++)                                    \
                MMA_TF32(acc[mt][nt], ah[mt], bh[nt]);                        \
        _Pragma("unroll")                                                     \
        for (int nt = 0; nt < 4; nt++) {                                      \
            const float* p = BsL_ + (wn*32 + nt*8 + g) * SSTRIDE + (ks)*8 + t;  \
            bl[nt][0] = __float_as_uint(p[0]);                                \
            bl[nt][1] = __float_as_uint(p[4]);                                \
        }                                                                     \
        _Pragma("unroll")                                                     \
        for (int mt = 0; mt < 4; mt++)                                        \
            _Pragma("unroll")                                                 \
            for (int nt = 0; nt < 4; nt++)                                    \
                MMA_TF32(acc[mt][nt], ah[mt], bl[nt]);                        \
        _Pragma("unroll")                                                     \
        for (int mt = 0; mt < 4; mt++) {                                      \
            const float* p = AsL_ + (wm*64 + mt*16 + g) * SSTRIDE + (ks)*8 + t; \
            al[mt][0] = __float_as_uint(p[0]);                                \
            al[mt][1] = __float_as_uint(p[8 * SSTRIDE]);                      \
            al[mt][2] = __float_as_uint(p[4]);                                \
            al[mt][3] = __float_as_uint(p[8 * SSTRIDE + 4]);                  \
        }                                                                     \
        _Pragma("unroll")                                                     \
        for (int mt = 0; mt < 4; mt++)                                        \
            _Pragma("unroll")                                                 \
            for (int nt = 0; nt < 4; nt++)                                    \
                MMA_TF32(acc[mt][nt], al[mt], bh[nt]);                        \
    } while (0)

    // prologue: tile 0 -> buffer 0
    LOADG(0);
    STORE_RR(0, 0); STORE_RR(1, 0); STORE_RR(2, 0); STORE_RR(3, 0);

    const int KT = K / BK;
    int cur = 0;
    for (int kt = 0; kt < KT; kt++) {
        __syncthreads();                     // buf[cur] visible; buf[cur^1] free
        const bool more = (kt + 1 < KT);
        if (more) LOADG((kt + 1) * BK);
        const int nxt = cur ^ 1;
        MMA_KS(0, cur);
        if (more) { STORE_RR(0, nxt); STORE_RR(1, nxt); }
        MMA_KS(1, cur);
        if (more) { STORE_RR(2, nxt); STORE_RR(3, nxt); }
        MMA_KS(2, cur);
        MMA_KS(3, cur);
        cur = nxt;
    }

    // ======================= epilogues =======================
    if (MODE == 0) {
        #pragma unroll
        for (int mt = 0; mt < 4; mt++) {
            const int row  = m0 + wm * 64 + mt * 16 + g;
            const int row2 = row + 8;
            const int am   = add_mod ? (row  % add_mod) : row;
            const int am2  = add_mod ? (row2 % add_mod) : row2;
            #pragma unroll
            for (int nt = 0; nt < 4; nt++) {
                const int col = n0 + wn * 32 + nt * 8 + 2 * t;
                float v0 = acc[mt][nt][0], v1 = acc[mt][nt][1];
                float v2 = acc[mt][nt][2], v3 = acc[mt][nt][3];
                if (add) {
                    v0 += add[(size_t)am  * N + col];
                    v1 += add[(size_t)am  * N + col + 1];
                    v2 += add[(size_t)am2 * N + col];
                    v3 += add[(size_t)am2 * N + col + 1];
                }
                if (bias1) {
                    v0 += bias1[col]; v1 += bias1[col + 1];
                    v2 += bias1[col]; v3 += bias1[col + 1];
                }
                if (bias2) {
                    v0 += bias2[col]; v1 += bias2[col + 1];
                    v2 += bias2[col]; v3 += bias2[col + 1];
                }
                *(float2*)(C + (size_t)row  * N + col) = make_float2(v0, v1);
                *(float2*)(C + (size_t)row2 * N + col) = make_float2(v2, v3);
            }
        }
    } else {
        // LSTM epilogue: cols are gate-permuted (col = jj*4 + G, G: i,f,g,o).
        // Lane pair (t, t^1): even lane holds (i,f), odd lane holds (g,o) of one jj.
        const bool even = ((t & 1) == 0);
        #pragma unroll
        for (int mt = 0; mt < 4; mt++) {
            const int row  = m0 + wm * 64 + mt * 16 + g;   // batch idx
            const int row2 = row + 8;
            #pragma unroll
            for (int nt = 0; nt < 4; nt++) {
                const int col = n0 + wn * 32 + nt * 8 + 2 * t;
                float v0 = acc[mt][nt][0] + add[(size_t)row  * N + col];
                float v1 = acc[mt][nt][1] + add[(size_t)row  * N + col + 1];
                float v2 = acc[mt][nt][2] + add[(size_t)row2 * N + col];
                float v3 = acc[mt][nt][3] + add[(size_t)row2 * N + col + 1];
                float q0 = __shfl_xor_sync(0xffffffffu, v0, 1);
                float q1 = __shfl_xor_sync(0xffffffffu, v1, 1);
                float q2 = __shfl_xor_sync(0xffffffffu, v2, 1);
                float q3 = __shfl_xor_sync(0xffffffffu, v3, 1);
                // even lane: row,  gates i=v0 f=v1 g=q0 o=q1
                // odd  lane: row2, gates i=q2 f=q3 g=v2 o=v3
                float gi = even ? v0 : q2;
                float gf = even ? v1 : q3;
                float gg = even ? q0 : v2;
                float go = even ? q1 : v3;
                const int r  = even ? row : row2;
                const int jj = (n0 + wn * 32 + nt * 8 + ((t & 2) << 1)) >> 2;
                float si = sigf(gi), sf = sigf(gf), so = sigf(go);
                float tg = tanh_fast(gg);
                const size_t ci = (size_t)r * H_SZ + jj;
                float cn = sf * cst[ci] + si * tg;
                cst[ci] = cn;
                float hn = so * tanh_fast(cn);
                hst[ci] = hn;
                outp[(size_t)r * T_STEPS * H_SZ + (size_t)tstep * H_SZ + jj] = hn;
            }
        }
    }
#undef LOADG
#undef STORE_RR
#undef MMA_KS
}

// ---------------- weight gate-permutation prep -----------------------------
// Wp[jj*4+G, :] = W[G*H+jj, :]
__global__ void permute_w(const float* __restrict__ W, float* __restrict__ Wp, int K)
{
    const int r  = blockIdx.x;          // permuted row
    const int jj = r >> 2, G = r & 3;
    const float4* s = (const float4*)(W + (size_t)(G * H_SZ + jj) * K);
    float4* d = (float4*)(Wp + (size_t)r * K);
    for (int k = threadIdx.x; k < K / 4; k += blockDim.x) d[k] = s[k];
}

__global__ void permute_bias(const float* __restrict__ b_ih,
                             const float* __restrict__ b_hh,
                             float* __restrict__ bp)
{
    int r = blockIdx.x * blockDim.x + threadIdx.x;   // permuted idx
    int jj = r >> 2, G = r & 3;
    bp[r] = b_ih[G * H_SZ + jj] + b_hh[G * H_SZ + jj];
}

// ---------------- pooled mean over masked timesteps -----------------------
__global__ void pooled_kernel(const float* __restrict__ dh,
                              const int* __restrict__ cap,
                              float* __restrict__ pooled)
{
    int b = blockIdx.y;
    int d = blockIdx.x * blockDim.x + threadIdx.x;
    float acc = 0.f, len = 0.f;
    #pragma unroll
    for (int t = 0; t < T_STEPS; t++) {
        int v = cap[t * B_SZ + b];
        float m = (v != 0 && v != 2) ? 1.f : 0.f;
        len += m;
        acc += m * dh[(size_t)t * B_SZ * D_SZ + (size_t)b * D_SZ + d];
    }
    pooled[(size_t)b * D_SZ + d] = acc / len;
}

// ---------------- zero h0, c, and out[:, 0, :] ------------------------------
__global__ void init_kernel(float* __restrict__ h, float* __restrict__ c,
                            float* __restrict__ out)
{
    int idx = blockIdx.x * blockDim.x + threadIdx.x;
    h[idx] = 0.f;
    c[idx] = 0.f;
    int b = idx >> 10;
    int j = idx & 1023;
    out[(size_t)b * T_STEPS * H_SZ + j] = 0.f;
}

// ---------------------------------------------------------------------------
extern "C" void kernel_launch(void* const* d_in, const int* in_sizes, int n_in,
                              void* d_out, int out_size)
{
    const float* dh    = (const float*)d_in[0];      // [T,1,B,D] == [T,B,D]
    const int*   cap   = (const int*)d_in[2];        // [T,B] int32
    const float* W_ih  = (const float*)d_in[3];      // [4H, 2D]
    const float* W_hh  = (const float*)d_in[4];      // [4H, H]
    const float* b_ih  = (const float*)d_in[5];      // [4H]
    const float* b_hh  = (const float*)d_in[6];      // [4H]
    float*       out   = (float*)d_out;              // [B, T, H]

    float *pooled, *Gpool, *Gin, *h, *c, *Wihp, *Whhp, *biasp;
    cudaGetSymbolAddress((void**)&pooled, g_pooled);
    cudaGetSymbolAddress((void**)&Gpool,  g_Gpool);
    cudaGetSymbolAddress((void**)&Gin,    g_Gin);
    cudaGetSymbolAddress((void**)&h,      g_h);
    cudaGetSymbolAddress((void**)&c,      g_c);
    cudaGetSymbolAddress((void**)&Wihp,   g_Wih_p);
    cudaGetSymbolAddress((void**)&Whhp,   g_Whh_p);
    cudaGetSymbolAddress((void**)&biasp,  g_bias_p);

    cudaFuncSetAttribute(gemm_mma<0>, cudaFuncAttributeMaxDynamicSharedMemorySize, SMEM_B);
    cudaFuncSetAttribute(gemm_mma<1>, cudaFuncAttributeMaxDynamicSharedMemorySize, SMEM_B);

    // 0) gate-permute weights and biases
    permute_w<<<G4, 256>>>(W_ih, Wihp, 2 * D_SZ);
    permute_w<<<G4, 256>>>(W_hh, Whhp, H_SZ);
    permute_bias<<<G4 / 256, 256>>>(b_ih, b_hh, biasp);

    // 1) pooled mean over masked timesteps
    pooled_kernel<<<dim3(D_SZ / 256, B_SZ), 256>>>(dh, cap, pooled);

    // 2) zero h[0], c, out[:,0,:]
    init_kernel<<<(B_SZ * H_SZ) / 256, 256>>>(h, c, out);

    // 3) Gpool = pooled @ Wihp[:, D:]^T + bias_p      (constant across t)
    gemm_mma<0><<<dim3(G4 / 128, B_SZ / 128), 256, SMEM_B>>>(
        pooled, D_SZ, Wihp + D_SZ, 2 * D_SZ,
        nullptr, 0, biasp, nullptr, Gpool, G4, D_SZ,
        nullptr, nullptr, nullptr, 0);

    // 4) Gin[t-1] = dh[t] @ Wihp[:, :D]^T + Gpool     (one big parallel GEMM)
    gemm_mma<0><<<dim3(G4 / 128, ((T_STEPS - 1) * B_SZ) / 128), 256, SMEM_B>>>(
        dh + (size_t)B_SZ * D_SZ, D_SZ, Wihp, 2 * D_SZ,
        Gpool, B_SZ, nullptr, nullptr, Gin, G4, D_SZ,
        nullptr, nullptr, nullptr, 0);

    // 5) recurrence: fused  gates = h @ Whhp^T + Gin[t]  -> LSTM update -> h,c,out
    //    h ping-pongs between g_h[0] and g_h[1] (cross-CTA RAW safety).
    for (int t = 1; t < T_STEPS; t++) {
        float* h_in  = h + ((t + 1) & 1) * (B_SZ * H_SZ);
        float* h_out = h + (t & 1) * (B_SZ * H_SZ);
        gemm_mma<1><<<dim3(G4 / 128, B_SZ / 128), 256, SMEM_B>>>(
            h_in, H_SZ, Whhp, H_SZ,
            Gin + (size_t)(t - 1) * B_SZ * G4, 0, nullptr, nullptr,
            nullptr, G4, H_SZ,
            c, h_out, out, t);
    }
}

// round 6
// speedup vs baseline: 1.0995x; 1.0995x over previous
#include <cuda_runtime.h>
#include <cstdint>

#define T_STEPS 48
#define B_SZ    512
#define D_SZ    1024
#define H_SZ    1024
#define G4      (4 * H_SZ)

// ---------------- scratch (static device globals; no allocation) ----------
__device__ float g_pooled[B_SZ * D_SZ];                       // 2 MB
__device__ float g_Gpool [B_SZ * G4];                         // 8 MB
__device__ float g_Gin   [(size_t)(T_STEPS - 1) * B_SZ * G4]; // ~386 MB
__device__ float g_h     [2][B_SZ * H_SZ];                    // 4 MB ping-pong
__device__ float g_c     [B_SZ * H_SZ];                       // 2 MB
__device__ float g_Wih_p [(size_t)G4 * 2 * D_SZ];             // 32 MB (gate-permuted)
__device__ float g_Whh_p [(size_t)G4 * H_SZ];                 // 16 MB (gate-permuted)
__device__ float g_bias_p[G4];                                // combined permuted bias

// ===================== helpers =============================================
__device__ __forceinline__ float tf32_round(float x) {
    float y; asm("cvt.rna.tf32.f32 %0, %1;" : "=f"(y) : "f"(x)); return y;
}
__device__ __forceinline__ float sigf(float x) {
    return 1.f / (1.f + __expf(-x));
}
__device__ __forceinline__ float tanh_fast(float x) {
    float e = __expf(2.f * x);          // safe at +-inf
    return 1.f - 2.f / (e + 1.f);
}

// mma.sync m16n8k8 tf32: D += A*B (row.col), fp32 accumulate
#define MMA_TF32(d, a, b)                                                     \
    asm volatile(                                                             \
        "mma.sync.aligned.m16n8k8.row.col.f32.tf32.tf32.f32 "                 \
        "{%0,%1,%2,%3}, {%4,%5,%6,%7}, {%8,%9}, {%0,%1,%2,%3};"               \
        : "+f"((d)[0]), "+f"((d)[1]), "+f"((d)[2]), "+f"((d)[3])              \
        : "r"((a)[0]), "r"((a)[1]), "r"((a)[2]), "r"((a)[3]),                 \
          "r"((b)[0]), "r"((b)[1]))

// ===================== tensor-core tf32 split-fp32 GEMM ====================
// C[M,N] = A[M,K] @ W[N,K]^T, tile 128x128, BK=32, 8 warps (2x4), 64x32 warp tile.
// Split: x = hi + lo; D += Ah*Bh + Ah*Bl + Al*Bh  (err ~2^-21).
// R4 mainloop structure (measured-good): single buffer, sync-store-sync,
// register prefetch dropped before the MMA region.
// MODE 0: C = acc (+add[row(%add_mod)]) (+bias1)
// MODE 1: LSTM step epilogue on gate-permuted cols (jj*4+G): h,c,out update.
#define BK       32
#define SSTRIDE  36   // floats; conflict-free frags; 16B aligned
#define TILE_F   (128 * SSTRIDE)
#define SMEM_B   (4 * TILE_F * 4)            // 73728 bytes

template<int MODE>
__global__ __launch_bounds__(256)
void gemm_mma(const float* __restrict__ A, int lda,
              const float* __restrict__ W, int ldw,
              const float* __restrict__ add, int add_mod,
              const float* __restrict__ bias1,
              float* __restrict__ C, int N, int K,
              float* __restrict__ cst, float* __restrict__ hst,
              float* __restrict__ outp, int tstep)
{
    extern __shared__ float sm[];
    float* AsH = sm;
    float* AsL = sm + TILE_F;
    float* BsH = sm + 2 * TILE_F;
    float* BsL = sm + 3 * TILE_F;

    const int tid = threadIdx.x;
    const int wid = tid >> 5, lid = tid & 31;
    const int wm  = wid >> 2, wn = wid & 3;       // 2x4 warp grid
    const int g   = lid >> 2, t  = lid & 3;       // mma lane decomposition
    const int m0  = blockIdx.y * 128;
    const int n0  = blockIdx.x * 128;

    // loader mapping: 256 threads cover 128 rows x 8 float4 (32 cols)
    const int j  = tid & 7;
    const int r0 = tid >> 3;

    float acc[4][4][4];
    #pragma unroll
    for (int a_ = 0; a_ < 4; a_++)
        #pragma unroll
        for (int b_ = 0; b_ < 4; b_++)
            #pragma unroll
            for (int e = 0; e < 4; e++) acc[a_][b_][e] = 0.f;

    const float* Abase = A + (size_t)(m0 + r0) * lda + j * 4;
    const float* Wbase = W + (size_t)(n0 + r0) * ldw + j * 4;

    float4 pa[4], pw[4];
    #pragma unroll
    for (int rr = 0; rr < 4; rr++) {
        pa[rr] = *(const float4*)(Abase + (size_t)rr * 32 * lda);
        pw[rr] = *(const float4*)(Wbase + (size_t)rr * 32 * ldw);
    }

    const int KT = K / BK;
    for (int kt = 0; kt < KT; kt++) {
        __syncthreads();   // previous compute done before overwriting smem
        #pragma unroll
        for (int rr = 0; rr < 4; rr++) {
            const int r = r0 + rr * 32;
            float4 v = pa[rr], hi, lo;
            hi.x = tf32_round(v.x); lo.x = tf32_round(v.x - hi.x);
            hi.y = tf32_round(v.y); lo.y = tf32_round(v.y - hi.y);
            hi.z = tf32_round(v.z); lo.z = tf32_round(v.z - hi.z);
            hi.w = tf32_round(v.w); lo.w = tf32_round(v.w - hi.w);
            *(float4*)(AsH + r * SSTRIDE + j * 4) = hi;
            *(float4*)(AsL + r * SSTRIDE + j * 4) = lo;
            v = pw[rr];
            hi.x = tf32_round(v.x); lo.x = tf32_round(v.x - hi.x);
            hi.y = tf32_round(v.y); lo.y = tf32_round(v.y - hi.y);
            hi.z = tf32_round(v.z); lo.z = tf32_round(v.z - hi.z);
            hi.w = tf32_round(v.w); lo.w = tf32_round(v.w - hi.w);
            *(float4*)(BsH + r * SSTRIDE + j * 4) = hi;
            *(float4*)(BsL + r * SSTRIDE + j * 4) = lo;
        }
        __syncthreads();

        if (kt + 1 < KT) {   // prefetch next k-slab; overlaps with MMA below
            const int ko = (kt + 1) * BK;
            #pragma unroll
            for (int rr = 0; rr < 4; rr++) {
                pa[rr] = *(const float4*)(Abase + (size_t)rr * 32 * lda + ko);
                pw[rr] = *(const float4*)(Wbase + (size_t)rr * 32 * ldw + ko);
            }
        }

        #pragma unroll
        for (int ks = 0; ks < 4; ks++) {
            uint32_t ah[4][4], al[4][4], bh[4][2], bl[4][2];
            #pragma unroll
            for (int mt = 0; mt < 4; mt++) {
                const float* p = AsH + (wm * 64 + mt * 16 + g) * SSTRIDE + ks * 8 + t;
                ah[mt][0] = __float_as_uint(p[0]);
                ah[mt][1] = __float_as_uint(p[8 * SSTRIDE]);
                ah[mt][2] = __float_as_uint(p[4]);
                ah[mt][3] = __float_as_uint(p[8 * SSTRIDE + 4]);
            }
            #pragma unroll
            for (int nt = 0; nt < 4; nt++) {
                const float* p = BsH + (wn * 32 + nt * 8 + g) * SSTRIDE + ks * 8 + t;
                bh[nt][0] = __float_as_uint(p[0]);
                bh[nt][1] = __float_as_uint(p[4]);
            }
            #pragma unroll
            for (int mt = 0; mt < 4; mt++)
                #pragma unroll
                for (int nt = 0; nt < 4; nt++)
                    MMA_TF32(acc[mt][nt], ah[mt], bh[nt]);

            #pragma unroll
            for (int nt = 0; nt < 4; nt++) {
                const float* p = BsL + (wn * 32 + nt * 8 + g) * SSTRIDE + ks * 8 + t;
                bl[nt][0] = __float_as_uint(p[0]);
                bl[nt][1] = __float_as_uint(p[4]);
            }
            #pragma unroll
            for (int mt = 0; mt < 4; mt++)
                #pragma unroll
                for (int nt = 0; nt < 4; nt++)
                    MMA_TF32(acc[mt][nt], ah[mt], bl[nt]);

            #pragma unroll
            for (int mt = 0; mt < 4; mt++) {
                const float* p = AsL + (wm * 64 + mt * 16 + g) * SSTRIDE + ks * 8 + t;
                al[mt][0] = __float_as_uint(p[0]);
                al[mt][1] = __float_as_uint(p[8 * SSTRIDE]);
                al[mt][2] = __float_as_uint(p[4]);
                al[mt][3] = __float_as_uint(p[8 * SSTRIDE + 4]);
            }
            #pragma unroll
            for (int mt = 0; mt < 4; mt++)
                #pragma unroll
                for (int nt = 0; nt < 4; nt++)
                    MMA_TF32(acc[mt][nt], al[mt], bh[nt]);
        }
    }

    // ======================= epilogues =======================
    if (MODE == 0) {
        #pragma unroll
        for (int mt = 0; mt < 4; mt++) {
            const int row  = m0 + wm * 64 + mt * 16 + g;
            const int row2 = row + 8;
            const int am   = add_mod ? (row  % add_mod) : row;
            const int am2  = add_mod ? (row2 % add_mod) : row2;
            #pragma unroll
            for (int nt = 0; nt < 4; nt++) {
                const int col = n0 + wn * 32 + nt * 8 + 2 * t;
                float v0 = acc[mt][nt][0], v1 = acc[mt][nt][1];
                float v2 = acc[mt][nt][2], v3 = acc[mt][nt][3];
                if (add) {
                    v0 += add[(size_t)am  * N + col];
                    v1 += add[(size_t)am  * N + col + 1];
                    v2 += add[(size_t)am2 * N + col];
                    v3 += add[(size_t)am2 * N + col + 1];
                }
                if (bias1) {
                    v0 += bias1[col]; v1 += bias1[col + 1];
                    v2 += bias1[col]; v3 += bias1[col + 1];
                }
                *(float2*)(C + (size_t)row  * N + col) = make_float2(v0, v1);
                *(float2*)(C + (size_t)row2 * N + col) = make_float2(v2, v3);
            }
        }
    } else {
        // LSTM epilogue: cols gate-permuted (col = jj*4 + G, G: i,f,g,o).
        // Lane pair (t, t^1): even lane holds (i,f), odd lane holds (g,o).
        const bool even = ((t & 1) == 0);
        #pragma unroll
        for (int mt = 0; mt < 4; mt++) {
            const int row  = m0 + wm * 64 + mt * 16 + g;   // batch idx
            const int row2 = row + 8;
            #pragma unroll
            for (int nt = 0; nt < 4; nt++) {
                const int col = n0 + wn * 32 + nt * 8 + 2 * t;
                float v0 = acc[mt][nt][0] + add[(size_t)row  * N + col];
                float v1 = acc[mt][nt][1] + add[(size_t)row  * N + col + 1];
                float v2 = acc[mt][nt][2] + add[(size_t)row2 * N + col];
                float v3 = acc[mt][nt][3] + add[(size_t)row2 * N + col + 1];
                float q0 = __shfl_xor_sync(0xffffffffu, v0, 1);
                float q1 = __shfl_xor_sync(0xffffffffu, v1, 1);
                float q2 = __shfl_xor_sync(0xffffffffu, v2, 1);
                float q3 = __shfl_xor_sync(0xffffffffu, v3, 1);
                float gi = even ? v0 : q2;
                float gf = even ? v1 : q3;
                float gg = even ? q0 : v2;
                float go = even ? q1 : v3;
                const int r  = even ? row : row2;
                const int jj = (n0 + wn * 32 + nt * 8 + ((t & 2) << 1)) >> 2;
                float si = sigf(gi), sf = sigf(gf), so = sigf(go);
                float tg = tanh_fast(gg);
                const size_t ci = (size_t)r * H_SZ + jj;
                float cn = sf * cst[ci] + si * tg;
                cst[ci] = cn;
                float hn = so * tanh_fast(cn);
                hst[ci] = hn;
                outp[(size_t)r * T_STEPS * H_SZ + (size_t)tstep * H_SZ + jj] = hn;
            }
        }
    }
}

// ---------------- weight gate-permutation prep -----------------------------
// Wp[jj*4+G, :] = W[G*H+jj, :]
__global__ void permute_w(const float* __restrict__ W, float* __restrict__ Wp, int K)
{
    const int r  = blockIdx.x;          // permuted row
    const int jj = r >> 2, G = r & 3;
    const float4* s = (const float4*)(W + (size_t)(G * H_SZ + jj) * K);
    float4* d = (float4*)(Wp + (size_t)r * K);
    for (int k = threadIdx.x; k < K / 4; k += blockDim.x) d[k] = s[k];
}

__global__ void permute_bias(const float* __restrict__ b_ih,
                             const float* __restrict__ b_hh,
                             float* __restrict__ bp)
{
    int r = blockIdx.x * blockDim.x + threadIdx.x;
    int jj = r >> 2, G = r & 3;
    bp[r] = b_ih[G * H_SZ + jj] + b_hh[G * H_SZ + jj];
}

// ---------------- pooled mean over masked timesteps -----------------------
__global__ void pooled_kernel(const float* __restrict__ dh,
                              const int* __restrict__ cap,
                              float* __restrict__ pooled)
{
    int b = blockIdx.y;
    int d = blockIdx.x * blockDim.x + threadIdx.x;
    float acc = 0.f, len = 0.f;
    #pragma unroll
    for (int t = 0; t < T_STEPS; t++) {
        int v = cap[t * B_SZ + b];
        float m = (v != 0 && v != 2) ? 1.f : 0.f;
        len += m;
        acc += m * dh[(size_t)t * B_SZ * D_SZ + (size_t)b * D_SZ + d];
    }
    pooled[(size_t)b * D_SZ + d] = acc / len;
}

// ---------------- zero c, out[:, 0, :] --------------------------------------
__global__ void init_kernel(float* __restrict__ c, float* __restrict__ out)
{
    int idx = blockIdx.x * blockDim.x + threadIdx.x;
    c[idx] = 0.f;
    int b = idx >> 10;
    int j = idx & 1023;
    out[(size_t)b * T_STEPS * H_SZ + j] = 0.f;
}

// ---------------- t=1 special step: h0=0, c0=0 ------------------------------
// gates = Gin[0] (permuted cols); c1 = sig(i)*tanh(g); h1 = sig(o)*tanh(c1)
__global__ void lstm_step1(const float* __restrict__ gin0,
                           float* __restrict__ c, float* __restrict__ h,
                           float* __restrict__ out)
{
    int idx = blockIdx.x * blockDim.x + threadIdx.x;   // over B*H
    int b = idx >> 10;
    int jj = idx & 1023;
    float4 gq = *(const float4*)(gin0 + (size_t)b * G4 + jj * 4);  // i,f,g,o
    float si = sigf(gq.x), so = sigf(gq.w);
    float cn = si * tanh_fast(gq.z);
    c[idx] = cn;
    float hn = so * tanh_fast(cn);
    h[idx] = hn;
    out[(size_t)b * T_STEPS * H_SZ + (size_t)H_SZ + jj] = hn;   // t=1
}

// ---------------------------------------------------------------------------
extern "C" void kernel_launch(void* const* d_in, const int* in_sizes, int n_in,
                              void* d_out, int out_size)
{
    const float* dh    = (const float*)d_in[0];      // [T,1,B,D] == [T,B,D]
    const int*   cap   = (const int*)d_in[2];        // [T,B] int32
    const float* W_ih  = (const float*)d_in[3];      // [4H, 2D]
    const float* W_hh  = (const float*)d_in[4];      // [4H, H]
    const float* b_ih  = (const float*)d_in[5];      // [4H]
    const float* b_hh  = (const float*)d_in[6];      // [4H]
    float*       out   = (float*)d_out;              // [B, T, H]

    float *pooled, *Gpool, *Gin, *h, *c, *Wihp, *Whhp, *biasp;
    cudaGetSymbolAddress((void**)&pooled, g_pooled);
    cudaGetSymbolAddress((void**)&Gpool,  g_Gpool);
    cudaGetSymbolAddress((void**)&Gin,    g_Gin);
    cudaGetSymbolAddress((void**)&h,      g_h);
    cudaGetSymbolAddress((void**)&c,      g_c);
    cudaGetSymbolAddress((void**)&Wihp,   g_Wih_p);
    cudaGetSymbolAddress((void**)&Whhp,   g_Whh_p);
    cudaGetSymbolAddress((void**)&biasp,  g_bias_p);

    cudaFuncSetAttribute(gemm_mma<0>, cudaFuncAttributeMaxDynamicSharedMemorySize, SMEM_B);
    cudaFuncSetAttribute(gemm_mma<1>, cudaFuncAttributeMaxDynamicSharedMemorySize, SMEM_B);

    // 0) gate-permute weights and biases
    permute_w<<<G4, 256>>>(W_ih, Wihp, 2 * D_SZ);
    permute_w<<<G4, 256>>>(W_hh, Whhp, H_SZ);
    permute_bias<<<G4 / 256, 256>>>(b_ih, b_hh, biasp);

    // 1) pooled mean over masked timesteps
    pooled_kernel<<<dim3(D_SZ / 256, B_SZ), 256>>>(dh, cap, pooled);

    // 2) zero c, out[:,0,:]
    init_kernel<<<(B_SZ * H_SZ) / 256, 256>>>(c, out);

    // 3) Gpool = pooled @ Wihp[:, D:]^T + bias_p      (constant across t)
    gemm_mma<0><<<dim3(G4 / 128, B_SZ / 128), 256, SMEM_B>>>(
        pooled, D_SZ, Wihp + D_SZ, 2 * D_SZ,
        nullptr, 0, biasp, Gpool, G4, D_SZ,
        nullptr, nullptr, nullptr, 0);

    // 4) Gin[t-1] = dh[t] @ Wihp[:, :D]^T + Gpool     (one big parallel GEMM)
    gemm_mma<0><<<dim3(G4 / 128, ((T_STEPS - 1) * B_SZ) / 128), 256, SMEM_B>>>(
        dh + (size_t)B_SZ * D_SZ, D_SZ, Wihp, 2 * D_SZ,
        Gpool, B_SZ, nullptr, Gin, G4, D_SZ,
        nullptr, nullptr, nullptr, 0);

    // 5a) t=1: h0=0, c0=0 -> pointwise only (skips one full step GEMM)
    lstm_step1<<<(B_SZ * H_SZ) / 256, 256>>>(Gin, c, h + B_SZ * H_SZ, out);

    // 5b) t=2..T-1: fused  gates = h @ Whhp^T + Gin[t] -> LSTM update -> h,c,out
    //     h ping-pongs between g_h[0] and g_h[1] (cross-CTA RAW safety).
    for (int t = 2; t < T_STEPS; t++) {
        float* h_in  = h + ((t + 1) & 1) * (B_SZ * H_SZ);
        float* h_out = h + (t & 1) * (B_SZ * H_SZ);
        gemm_mma<1><<<dim3(G4 / 128, B_SZ / 128), 256, SMEM_B>>>(
            h_in, H_SZ, Whhp, H_SZ,
            Gin + (size_t)(t - 1) * B_SZ * G4, 0, nullptr,
            nullptr, G4, H_SZ,
            c, h_out, out, t);
    }
}

// round 7
// speedup vs baseline: 1.1533x; 1.0490x over previous
#include <cuda_runtime.h>
#include <cstdint>

#define T_STEPS 48
#define B_SZ    512
#define D_SZ    1024
#define H_SZ    1024
#define G4      (4 * H_SZ)

// ---------------- scratch (static device globals; no allocation) ----------
__device__ float g_pooled[B_SZ * D_SZ];                       // 2 MB
__device__ float g_Gpool [B_SZ * G4];                         // 8 MB
__device__ float g_Gin   [(size_t)(T_STEPS - 1) * B_SZ * G4]; // ~386 MB
__device__ float g_h     [2][B_SZ * H_SZ];                    // 4 MB ping-pong
__device__ float g_c     [B_SZ * H_SZ];                       // 2 MB
__device__ float g_Wih_p [(size_t)G4 * 2 * D_SZ];             // 32 MB (gate-permuted)
__device__ float g_Whh_p [(size_t)G4 * H_SZ];                 // 16 MB (gate-permuted)
__device__ float g_bias_p[G4];                                // combined permuted bias

// ===================== helpers =============================================
__device__ __forceinline__ float tf32_round(float x) {
    float y; asm("cvt.rna.tf32.f32 %0, %1;" : "=f"(y) : "f"(x)); return y;
}
__device__ __forceinline__ float sigf(float x) {
    return 1.f / (1.f + __expf(-x));
}
__device__ __forceinline__ float tanh_fast(float x) {
    float e = __expf(2.f * x);          // safe at +-inf
    return 1.f - 2.f / (e + 1.f);
}
__device__ __forceinline__ uint32_t smem_u32(const void* p) {
    uint32_t a;
    asm("{ .reg .u64 t; cvta.to.shared.u64 t, %1; cvt.u32.u64 %0, t; }"
        : "=r"(a) : "l"(p));
    return a;
}
__device__ __forceinline__ void cp16(uint32_t dst, const void* src) {
    asm volatile("cp.async.ca.shared.global [%0], [%1], 16;" :: "r"(dst), "l"(src));
}
#define CP_COMMIT() asm volatile("cp.async.commit_group;" ::: "memory")
#define CP_WAIT(n)  asm volatile("cp.async.wait_group %0;" :: "n"(n) : "memory")

// split fp32 -> (tf32 hi, residual lo); MMA HW truncates lo to tf32 (err ~2^-21)
#define SPLIT(f, hv, lv) do { float _h = tf32_round(f); \
    hv = __float_as_uint(_h); lv = __float_as_uint((f) - _h); } while (0)

// mma.sync m16n8k8 tf32: D += A*B (row.col), fp32 accumulate
#define MMA_TF32(d, a, b)                                                     \
    asm volatile(                                                             \
        "mma.sync.aligned.m16n8k8.row.col.f32.tf32.tf32.f32 "                 \
        "{%0,%1,%2,%3}, {%4,%5,%6,%7}, {%8,%9}, {%0,%1,%2,%3};"               \
        : "+f"((d)[0]), "+f"((d)[1]), "+f"((d)[2]), "+f"((d)[3])              \
        : "r"((a)[0]), "r"((a)[1]), "r"((a)[2]), "r"((a)[3]),                 \
          "r"((b)[0]), "r"((b)[1]))

// ===================== tensor-core tf32 split-fp32 GEMM ====================
// C[M,N] = A[M,K] @ W[N,K]^T, tile 128x128, BK=32, 8 warps (2x4), 64x32 warp tile.
// cp.async double-buffered fp32 staging; hi/lo split at fragment load.
// 3-term split: D += Ah*Bh + Al*Bh + Ah*Bl  (err ~2^-21).
// MODE 0: C = acc (+add[row(%add_mod)]) (+bias1)
// MODE 1: LSTM step epilogue on gate-permuted cols (jj*4+G): h,c,out update.
#define BK       32
#define SSTRIDE  36                      // floats; conflict-free; 16B-aligned rows
#define STAGE_F  (128 * SSTRIDE)         // per-tile floats (4608)
#define STAGE_BY (2 * STAGE_F * 4)       // A+B per stage bytes (36864)
#define SMEM_B   (2 * STAGE_BY)          // 73728 bytes

template<int MODE>
__global__ __launch_bounds__(256, 2)
void gemm_mma(const float* __restrict__ A, int lda,
              const float* __restrict__ W, int ldw,
              const float* __restrict__ add, int add_mod,
              const float* __restrict__ bias1,
              float* __restrict__ C, int N, int K,
              float* __restrict__ cst, float* __restrict__ hst,
              float* __restrict__ outp, int tstep)
{
    extern __shared__ float sm[];
    const uint32_t sb = smem_u32(sm);

    const int tid = threadIdx.x;
    const int wid = tid >> 5, lid = tid & 31;
    const int wm  = wid >> 2, wn = wid & 3;       // 2x4 warp grid
    const int g   = lid >> 2, t  = lid & 3;       // mma lane decomposition
    const int m0  = blockIdx.y * 128;
    const int n0  = blockIdx.x * 128;

    // loader mapping: 256 threads cover 128 rows x 8 chunks of 16B (32 cols)
    const int j  = tid & 7;
    const int r0 = tid >> 3;

    float acc[4][4][4];
    #pragma unroll
    for (int a_ = 0; a_ < 4; a_++)
        #pragma unroll
        for (int b_ = 0; b_ < 4; b_++)
            #pragma unroll
            for (int e = 0; e < 4; e++) acc[a_][b_][e] = 0.f;

    const char* Ag = (const char*)(A + (size_t)(m0 + r0) * lda + j * 4);
    const char* Wg = (const char*)(W + (size_t)(n0 + r0) * ldw + j * 4);
    const uint32_t Ad = sb + (uint32_t)(r0 * SSTRIDE + j * 4) * 4;
    const uint32_t Bd = Ad + STAGE_F * 4;
    const size_t Astep = (size_t)32 * lda * 4;
    const size_t Wstep = (size_t)32 * ldw * 4;

    auto issue = [&](int kt, int s) {
        const char* a = Ag + (size_t)kt * BK * 4;
        const char* w = Wg + (size_t)kt * BK * 4;
        const uint32_t ad = Ad + s * STAGE_BY;
        const uint32_t bd = Bd + s * STAGE_BY;
        #pragma unroll
        for (int rr = 0; rr < 4; rr++) {
            cp16(ad + rr * 32 * SSTRIDE * 4, a + rr * Astep);
            cp16(bd + rr * 32 * SSTRIDE * 4, w + rr * Wstep);
        }
    };

    issue(0, 0); CP_COMMIT();

    const int KT = K / BK;
    for (int kt = 0; kt < KT; kt++) {
        if (kt + 1 < KT) { issue(kt + 1, (kt + 1) & 1); CP_COMMIT(); CP_WAIT(1); }
        else             { CP_WAIT(0); }
        __syncthreads();                          // stage kt visible to all

        const float* As_ = sm + (kt & 1) * (STAGE_BY / 4);
        const float* Bs_ = As_ + STAGE_F;

        #pragma unroll
        for (int ks = 0; ks < 4; ks++) {
            uint32_t bh[4][2], bl[4][2];
            #pragma unroll
            for (int nt = 0; nt < 4; nt++) {
                const float* p = Bs_ + (wn * 32 + nt * 8 + g) * SSTRIDE + ks * 8 + t;
                SPLIT(p[0], bh[nt][0], bl[nt][0]);
                SPLIT(p[4], bh[nt][1], bl[nt][1]);
            }
            #pragma unroll
            for (int mt = 0; mt < 4; mt++) {
                const float* p = As_ + (wm * 64 + mt * 16 + g) * SSTRIDE + ks * 8 + t;
                uint32_t ah[4], al[4];
                SPLIT(p[0],               ah[0], al[0]);
                SPLIT(p[8 * SSTRIDE],     ah[1], al[1]);
                SPLIT(p[4],               ah[2], al[2]);
                SPLIT(p[8 * SSTRIDE + 4], ah[3], al[3]);
                #pragma unroll
                for (int nt = 0; nt < 4; nt++) MMA_TF32(acc[mt][nt], ah, bh[nt]);
                #pragma unroll
                for (int nt = 0; nt < 4; nt++) MMA_TF32(acc[mt][nt], al, bh[nt]);
                #pragma unroll
                for (int nt = 0; nt < 4; nt++) MMA_TF32(acc[mt][nt], ah, bl[nt]);
            }
        }
        __syncthreads();                          // done with stage kt&1
    }

    // ======================= epilogues =======================
    if (MODE == 0) {
        #pragma unroll
        for (int mt = 0; mt < 4; mt++) {
            const int row  = m0 + wm * 64 + mt * 16 + g;
            const int row2 = row + 8;
            const int am   = add_mod ? (row  % add_mod) : row;
            const int am2  = add_mod ? (row2 % add_mod) : row2;
            #pragma unroll
            for (int nt = 0; nt < 4; nt++) {
                const int col = n0 + wn * 32 + nt * 8 + 2 * t;
                float v0 = acc[mt][nt][0], v1 = acc[mt][nt][1];
                float v2 = acc[mt][nt][2], v3 = acc[mt][nt][3];
                if (add) {
                    v0 += add[(size_t)am  * N + col];
                    v1 += add[(size_t)am  * N + col + 1];
                    v2 += add[(size_t)am2 * N + col];
                    v3 += add[(size_t)am2 * N + col + 1];
                }
                if (bias1) {
                    v0 += bias1[col]; v1 += bias1[col + 1];
                    v2 += bias1[col]; v3 += bias1[col + 1];
                }
                *(float2*)(C + (size_t)row  * N + col) = make_float2(v0, v1);
                *(float2*)(C + (size_t)row2 * N + col) = make_float2(v2, v3);
            }
        }
    } else {
        // LSTM epilogue: cols gate-permuted (col = jj*4 + G, G: i,f,g,o).
        // Lane pair (t, t^1): even lane holds (i,f), odd lane holds (g,o).
        const bool even = ((t & 1) == 0);
        #pragma unroll
        for (int mt = 0; mt < 4; mt++) {
            const int row  = m0 + wm * 64 + mt * 16 + g;   // batch idx
            const int row2 = row + 8;
            #pragma unroll
            for (int nt = 0; nt < 4; nt++) {
                const int col = n0 + wn * 32 + nt * 8 + 2 * t;
                float v0 = acc[mt][nt][0] + add[(size_t)row  * N + col];
                float v1 = acc[mt][nt][1] + add[(size_t)row  * N + col + 1];
                float v2 = acc[mt][nt][2] + add[(size_t)row2 * N + col];
                float v3 = acc[mt][nt][3] + add[(size_t)row2 * N + col + 1];
                float q0 = __shfl_xor_sync(0xffffffffu, v0, 1);
                float q1 = __shfl_xor_sync(0xffffffffu, v1, 1);
                float q2 = __shfl_xor_sync(0xffffffffu, v2, 1);
                float q3 = __shfl_xor_sync(0xffffffffu, v3, 1);
                float gi = even ? v0 : q2;
                float gf = even ? v1 : q3;
                float gg = even ? q0 : v2;
                float go = even ? q1 : v3;
                const int r  = even ? row : row2;
                const int jj = (n0 + wn * 32 + nt * 8 + ((t & 2) << 1)) >> 2;
                float si = sigf(gi), sf = sigf(gf), so = sigf(go);
                float tg = tanh_fast(gg);
                const size_t ci = (size_t)r * H_SZ + jj;
                float cn = sf * cst[ci] + si * tg;
                cst[ci] = cn;
                float hn = so * tanh_fast(cn);
                hst[ci] = hn;
                outp[(size_t)r * T_STEPS * H_SZ + (size_t)tstep * H_SZ + jj] = hn;
            }
        }
    }
}

// ---------------- weight gate-permutation prep -----------------------------
// Wp[jj*4+G, :] = W[G*H+jj, :]
__global__ void permute_w(const float* __restrict__ W, float* __restrict__ Wp, int K)
{
    const int r  = blockIdx.x;          // permuted row
    const int jj = r >> 2, G = r & 3;
    const float4* s = (const float4*)(W + (size_t)(G * H_SZ + jj) * K);
    float4* d = (float4*)(Wp + (size_t)r * K);
    for (int k = threadIdx.x; k < K / 4; k += blockDim.x) d[k] = s[k];
}

__global__ void permute_bias(const float* __restrict__ b_ih,
                             const float* __restrict__ b_hh,
                             float* __restrict__ bp)
{
    int r = blockIdx.x * blockDim.x + threadIdx.x;
    int jj = r >> 2, G = r & 3;
    bp[r] = b_ih[G * H_SZ + jj] + b_hh[G * H_SZ + jj];
}

// ---------------- pooled mean over masked timesteps (float4) ---------------
__global__ void pooled_kernel(const float* __restrict__ dh,
                              const int* __restrict__ cap,
                              float* __restrict__ pooled)
{
    int b  = blockIdx.y;
    int d4 = blockIdx.x * blockDim.x + threadIdx.x;   // over D/4
    float4 acc = make_float4(0.f, 0.f, 0.f, 0.f);
    float len = 0.f;
    #pragma unroll
    for (int t = 0; t < T_STEPS; t++) {
        int v = cap[t * B_SZ + b];
        float m = (v != 0 && v != 2) ? 1.f : 0.f;
        len += m;
        float4 x = *(const float4*)(dh + (size_t)t * B_SZ * D_SZ + (size_t)b * D_SZ + d4 * 4);
        acc.x += m * x.x; acc.y += m * x.y; acc.z += m * x.z; acc.w += m * x.w;
    }
    float inv = 1.f / len;
    *(float4*)(pooled + (size_t)b * D_SZ + d4 * 4) =
        make_float4(acc.x * inv, acc.y * inv, acc.z * inv, acc.w * inv);
}

// ---------------- zero c, out[:, 0, :] --------------------------------------
__global__ void init_kernel(float* __restrict__ c, float* __restrict__ out)
{
    int idx = blockIdx.x * blockDim.x + threadIdx.x;
    c[idx] = 0.f;
    int b = idx >> 10;
    int j = idx & 1023;
    out[(size_t)b * T_STEPS * H_SZ + j] = 0.f;
}

// ---------------- t=1 special step: h0=0, c0=0 ------------------------------
__global__ void lstm_step1(const float* __restrict__ gin0,
                           float* __restrict__ c, float* __restrict__ h,
                           float* __restrict__ out)
{
    int idx = blockIdx.x * blockDim.x + threadIdx.x;   // over B*H
    int b = idx >> 10;
    int jj = idx & 1023;
    float4 gq = *(const float4*)(gin0 + (size_t)b * G4 + jj * 4);  // i,f,g,o
    float si = sigf(gq.x), so = sigf(gq.w);
    float cn = si * tanh_fast(gq.z);
    c[idx] = cn;
    float hn = so * tanh_fast(cn);
    h[idx] = hn;
    out[(size_t)b * T_STEPS * H_SZ + (size_t)H_SZ + jj] = hn;   // t=1
}

// ---------------------------------------------------------------------------
extern "C" void kernel_launch(void* const* d_in, const int* in_sizes, int n_in,
                              void* d_out, int out_size)
{
    const float* dh    = (const float*)d_in[0];      // [T,1,B,D] == [T,B,D]
    const int*   cap   = (const int*)d_in[2];        // [T,B] int32
    const float* W_ih  = (const float*)d_in[3];      // [4H, 2D]
    const float* W_hh  = (const float*)d_in[4];      // [4H, H]
    const float* b_ih  = (const float*)d_in[5];      // [4H]
    const float* b_hh  = (const float*)d_in[6];      // [4H]
    float*       out   = (float*)d_out;              // [B, T, H]

    float *pooled, *Gpool, *Gin, *h, *c, *Wihp, *Whhp, *biasp;
    cudaGetSymbolAddress((void**)&pooled, g_pooled);
    cudaGetSymbolAddress((void**)&Gpool,  g_Gpool);
    cudaGetSymbolAddress((void**)&Gin,    g_Gin);
    cudaGetSymbolAddress((void**)&h,      g_h);
    cudaGetSymbolAddress((void**)&c,      g_c);
    cudaGetSymbolAddress((void**)&Wihp,   g_Wih_p);
    cudaGetSymbolAddress((void**)&Whhp,   g_Whh_p);
    cudaGetSymbolAddress((void**)&biasp,  g_bias_p);

    cudaFuncSetAttribute(gemm_mma<0>, cudaFuncAttributeMaxDynamicSharedMemorySize, SMEM_B);
    cudaFuncSetAttribute(gemm_mma<1>, cudaFuncAttributeMaxDynamicSharedMemorySize, SMEM_B);

    // 0) gate-permute weights and biases
    permute_w<<<G4, 256>>>(W_ih, Wihp, 2 * D_SZ);
    permute_w<<<G4, 256>>>(W_hh, Whhp, H_SZ);
    permute_bias<<<G4 / 256, 256>>>(b_ih, b_hh, biasp);

    // 1) pooled mean over masked timesteps
    pooled_kernel<<<dim3(1, B_SZ), 256>>>(dh, cap, pooled);

    // 2) zero c, out[:,0,:]
    init_kernel<<<(B_SZ * H_SZ) / 256, 256>>>(c, out);

    // 3) Gpool = pooled @ Wihp[:, D:]^T + bias_p      (constant across t)
    gemm_mma<0><<<dim3(G4 / 128, B_SZ / 128), 256, SMEM_B>>>(
        pooled, D_SZ, Wihp + D_SZ, 2 * D_SZ,
        nullptr, 0, biasp, Gpool, G4, D_SZ,
        nullptr, nullptr, nullptr, 0);

    // 4) Gin[t-1] = dh[t] @ Wihp[:, :D]^T + Gpool     (one big parallel GEMM)
    gemm_mma<0><<<dim3(G4 / 128, ((T_STEPS - 1) * B_SZ) / 128), 256, SMEM_B>>>(
        dh + (size_t)B_SZ * D_SZ, D_SZ, Wihp, 2 * D_SZ,
        Gpool, B_SZ, nullptr, Gin, G4, D_SZ,
        nullptr, nullptr, nullptr, 0);

    // 5a) t=1: h0=0, c0=0 -> pointwise only (skips one full step GEMM)
    lstm_step1<<<(B_SZ * H_SZ) / 256, 256>>>(Gin, c, h + B_SZ * H_SZ, out);

    // 5b) t=2..T-1: fused  gates = h @ Whhp^T + Gin[t] -> LSTM update -> h,c,out
    for (int t = 2; t < T_STEPS; t++) {
        float* h_in  = h + ((t + 1) & 1) * (B_SZ * H_SZ);
        float* h_out = h + (t & 1) * (B_SZ * H_SZ);
        gemm_mma<1><<<dim3(G4 / 128, B_SZ / 128), 256, SMEM_B>>>(
            h_in, H_SZ, Whhp, H_SZ,
            Gin + (size_t)(t - 1) * B_SZ * G4, 0, nullptr,
            nullptr, G4, H_SZ,
            c, h_out, out, t);
    }
}

// round 8
// speedup vs baseline: 1.5173x; 1.3156x over previous
#include <cuda_runtime.h>
#include <cstdint>

#define T_STEPS 48
#define B_SZ    512
#define D_SZ    1024
#define H_SZ    1024
#define G4      (4 * H_SZ)

// ---------------- scratch (static device globals; no allocation) ----------
__device__ float    g_Gpool [B_SZ * G4];                          // 8 MB
__device__ float    g_Gin   [(size_t)(T_STEPS - 1) * B_SZ * G4];  // ~386 MB
__device__ float    g_c     [B_SZ * H_SZ];                        // 2 MB
__device__ float    g_bias_p[G4];
// bf16 hi/lo operand planes
__device__ uint16_t g_wih_hi[(size_t)G4 * 2 * D_SZ];              // 16 MB
__device__ uint16_t g_wih_lo[(size_t)G4 * 2 * D_SZ];
__device__ uint16_t g_whh_hi[(size_t)G4 * H_SZ];                  // 8 MB
__device__ uint16_t g_whh_lo[(size_t)G4 * H_SZ];
__device__ uint16_t g_dh_hi [(size_t)(T_STEPS - 1) * B_SZ * D_SZ]; // 49 MB
__device__ uint16_t g_dh_lo [(size_t)(T_STEPS - 1) * B_SZ * D_SZ];
__device__ uint16_t g_pl_hi [B_SZ * D_SZ];                        // 1 MB
__device__ uint16_t g_pl_lo [B_SZ * D_SZ];
__device__ uint16_t g_h_hi  [2][B_SZ * H_SZ];                     // ping-pong
__device__ uint16_t g_h_lo  [2][B_SZ * H_SZ];

// ===================== helpers =============================================
__device__ __forceinline__ float sigf(float x) { return 1.f / (1.f + __expf(-x)); }
__device__ __forceinline__ float tanh_fast(float x) {
    float e = __expf(2.f * x);          // safe at +-inf
    return 1.f - 2.f / (e + 1.f);
}
__device__ __forceinline__ uint32_t smem_u32(const void* p) {
    uint32_t a;
    asm("{ .reg .u64 t; cvta.to.shared.u64 t, %1; cvt.u32.u64 %0, t; }"
        : "=r"(a) : "l"(p));
    return a;
}
__device__ __forceinline__ void cp16(uint32_t dst, const void* src) {
    asm volatile("cp.async.ca.shared.global [%0], [%1], 16;" :: "r"(dst), "l"(src));
}
#define CP_COMMIT() asm volatile("cp.async.commit_group;" ::: "memory")
#define CP_WAIT(n)  asm volatile("cp.async.wait_group %0;" :: "n"(n) : "memory")

// split two fp32 -> packed bf16x2 hi + bf16x2 lo (elem0 in low half)
__device__ __forceinline__ void bsplit2(float f0, float f1, uint32_t& hi, uint32_t& lo) {
    asm("cvt.rn.bf16x2.f32 %0, %1, %2;" : "=r"(hi) : "f"(f1), "f"(f0));
    float h0 = __uint_as_float(hi << 16);
    float h1 = __uint_as_float(hi & 0xFFFF0000u);
    float l0 = f0 - h0, l1 = f1 - h1;
    asm("cvt.rn.bf16x2.f32 %0, %1, %2;" : "=r"(lo) : "f"(l1), "f"(l0));
}
__device__ __forceinline__ void bsplit1(float f, uint16_t& hi, uint16_t& lo) {
    uint32_t hp;
    asm("cvt.rn.bf16x2.f32 %0, %1, %2;" : "=r"(hp) : "f"(0.f), "f"(f));
    float hf = __uint_as_float(hp << 16);
    uint32_t lp;
    float l = f - hf;
    asm("cvt.rn.bf16x2.f32 %0, %1, %2;" : "=r"(lp) : "f"(0.f), "f"(l));
    hi = (uint16_t)hp; lo = (uint16_t)lp;
}

// mma.sync m16n8k16 bf16: D += A*B (row.col), fp32 accumulate
#define MMA_BF16(d, a, b)                                                     \
    asm volatile(                                                             \
        "mma.sync.aligned.m16n8k16.row.col.f32.bf16.bf16.f32 "                \
        "{%0,%1,%2,%3}, {%4,%5,%6,%7}, {%8,%9}, {%0,%1,%2,%3};"               \
        : "+f"((d)[0]), "+f"((d)[1]), "+f"((d)[2]), "+f"((d)[3])              \
        : "r"((a)[0]), "r"((a)[1]), "r"((a)[2]), "r"((a)[3]),                 \
          "r"((b)[0]), "r"((b)[1]))

// ===================== bf16 split-fp32 GEMM =================================
// C[M,N] = A[M,K] @ W[N,K]^T with pre-split bf16 planes (hi/lo).
// 3 terms: D += Ah*Bh + Al*Bh + Ah*Bl  (err ~2^-16 per product, random sign).
// Tile 128x128, BK=32 (2 ks-slices of k16), 8 warps (2x4), warp tile 64x32.
// cp.async double-buffered; row stride 80 B -> all fragment LDS conflict-free.
// MODE 0: C = acc (+add[row % add_mod]) (+bias1)
// MODE 1: LSTM epilogue on gate-permuted cols (jj*4+G): c, h(hi/lo), out.
#define BK        32
#define ROW_BY    80                      // 64 B data + 16 pad
#define PLANE_BY  (128 * ROW_BY)          // 10240
#define STAGE_BY  (4 * PLANE_BY)          // Ahi, Alo, Bhi, Blo = 40960
#define SMEM_B    (2 * STAGE_BY)          // 81920

template<int MODE>
__global__ __launch_bounds__(256, 2)
void gemm_bf16(const uint16_t* __restrict__ Ahi, const uint16_t* __restrict__ Alo, int lda,
               const uint16_t* __restrict__ Whi, const uint16_t* __restrict__ Wlo, int ldw,
               const float* __restrict__ add, int add_mod,
               const float* __restrict__ bias1,
               float* __restrict__ C, int N, int K,
               float* __restrict__ cst,
               uint16_t* __restrict__ h_hi, uint16_t* __restrict__ h_lo,
               float* __restrict__ outp, int tstep)
{
    extern __shared__ char smc[];
    const uint32_t sb = smem_u32(smc);

    const int tid = threadIdx.x;
    const int wid = tid >> 5, lid = tid & 31;
    const int wm  = wid >> 2, wn = wid & 3;       // 2x4 warp grid
    const int g   = lid >> 2, t  = lid & 3;       // mma lane decomposition
    const int m0  = blockIdx.y * 128;
    const int n0  = blockIdx.x * 128;

    float acc[4][4][4];
    #pragma unroll
    for (int a_ = 0; a_ < 4; a_++)
        #pragma unroll
        for (int b_ = 0; b_ < 4; b_++)
            #pragma unroll
            for (int e = 0; e < 4; e++) acc[a_][b_][e] = 0.f;

    // loader: 256 threads; thread -> row r (0..127), 32-byte half jo (0/32)
    const int r  = tid >> 1;
    const int jo = (tid & 1) * 32;
    const char* pAh = (const char*)(Ahi + (size_t)(m0 + r) * lda) + jo;
    const char* pAl = (const char*)(Alo + (size_t)(m0 + r) * lda) + jo;
    const char* pBh = (const char*)(Whi + (size_t)(n0 + r) * ldw) + jo;
    const char* pBl = (const char*)(Wlo + (size_t)(n0 + r) * ldw) + jo;
    const uint32_t dbase = sb + (uint32_t)(r * ROW_BY + jo);

    auto issue = [&](int kt, int s) {
        const size_t ko = (size_t)kt * (BK * 2);   // bytes along K
        const uint32_t d0 = dbase + s * STAGE_BY;
        cp16(d0,                  pAh + ko);  cp16(d0 + 16,                  pAh + ko + 16);
        cp16(d0 + PLANE_BY,       pAl + ko);  cp16(d0 + PLANE_BY + 16,       pAl + ko + 16);
        cp16(d0 + 2 * PLANE_BY,   pBh + ko);  cp16(d0 + 2 * PLANE_BY + 16,   pBh + ko + 16);
        cp16(d0 + 3 * PLANE_BY,   pBl + ko);  cp16(d0 + 3 * PLANE_BY + 16,   pBl + ko + 16);
    };

    issue(0, 0); CP_COMMIT();

    const int KT = K / BK;
    for (int kt = 0; kt < KT; kt++) {
        if (kt + 1 < KT) { issue(kt + 1, (kt + 1) & 1); CP_COMMIT(); CP_WAIT(1); }
        else             { CP_WAIT(0); }
        __syncthreads();

        const char* st = smc + (kt & 1) * STAGE_BY;
        const char* sAh = st;
        const char* sAl = st + PLANE_BY;
        const char* sBh = st + 2 * PLANE_BY;
        const char* sBl = st + 3 * PLANE_BY;

        #pragma unroll
        for (int ks = 0; ks < 2; ks++) {
            const int kb = ks * 32 + t * 4;          // byte offset along K
            uint32_t bh[4][2], bl[4][2];
            #pragma unroll
            for (int nt = 0; nt < 4; nt++) {
                const int rowb = (wn * 32 + nt * 8 + g) * ROW_BY + kb;
                bh[nt][0] = *(const uint32_t*)(sBh + rowb);
                bh[nt][1] = *(const uint32_t*)(sBh + rowb + 16);
                bl[nt][0] = *(const uint32_t*)(sBl + rowb);
                bl[nt][1] = *(const uint32_t*)(sBl + rowb + 16);
            }
            #pragma unroll
            for (int mt = 0; mt < 4; mt++) {
                const int rowb = (wm * 64 + mt * 16 + g) * ROW_BY + kb;
                uint32_t ah[4], al[4];
                ah[0] = *(const uint32_t*)(sAh + rowb);
                ah[1] = *(const uint32_t*)(sAh + rowb + 8 * ROW_BY);
                ah[2] = *(const uint32_t*)(sAh + rowb + 16);
                ah[3] = *(const uint32_t*)(sAh + rowb + 8 * ROW_BY + 16);
                al[0] = *(const uint32_t*)(sAl + rowb);
                al[1] = *(const uint32_t*)(sAl + rowb + 8 * ROW_BY);
                al[2] = *(const uint32_t*)(sAl + rowb + 16);
                al[3] = *(const uint32_t*)(sAl + rowb + 8 * ROW_BY + 16);
                #pragma unroll
                for (int nt = 0; nt < 4; nt++) MMA_BF16(acc[mt][nt], ah, bh[nt]);
                #pragma unroll
                for (int nt = 0; nt < 4; nt++) MMA_BF16(acc[mt][nt], al, bh[nt]);
                #pragma unroll
                for (int nt = 0; nt < 4; nt++) MMA_BF16(acc[mt][nt], ah, bl[nt]);
            }
        }
        __syncthreads();
    }

    // ======================= epilogues =======================
    if (MODE == 0) {
        #pragma unroll
        for (int mt = 0; mt < 4; mt++) {
            const int row  = m0 + wm * 64 + mt * 16 + g;
            const int row2 = row + 8;
            const int am   = add_mod ? (row  % add_mod) : row;
            const int am2  = add_mod ? (row2 % add_mod) : row2;
            #pragma unroll
            for (int nt = 0; nt < 4; nt++) {
                const int col = n0 + wn * 32 + nt * 8 + 2 * t;
                float v0 = acc[mt][nt][0], v1 = acc[mt][nt][1];
                float v2 = acc[mt][nt][2], v3 = acc[mt][nt][3];
                if (add) {
                    v0 += add[(size_t)am  * N + col];
                    v1 += add[(size_t)am  * N + col + 1];
                    v2 += add[(size_t)am2 * N + col];
                    v3 += add[(size_t)am2 * N + col + 1];
                }
                if (bias1) {
                    v0 += bias1[col]; v1 += bias1[col + 1];
                    v2 += bias1[col]; v3 += bias1[col + 1];
                }
                *(float2*)(C + (size_t)row  * N + col) = make_float2(v0, v1);
                *(float2*)(C + (size_t)row2 * N + col) = make_float2(v2, v3);
            }
        }
    } else {
        // LSTM epilogue: cols gate-permuted (col = jj*4 + G, G: i,f,g,o).
        // Lane pair (t, t^1): even lane holds (i,f), odd lane holds (g,o).
        const bool even = ((t & 1) == 0);
        #pragma unroll
        for (int mt = 0; mt < 4; mt++) {
            const int row  = m0 + wm * 64 + mt * 16 + g;   // batch idx
            const int row2 = row + 8;
            #pragma unroll
            for (int nt = 0; nt < 4; nt++) {
                const int col = n0 + wn * 32 + nt * 8 + 2 * t;
                float v0 = acc[mt][nt][0] + add[(size_t)row  * N + col];
                float v1 = acc[mt][nt][1] + add[(size_t)row  * N + col + 1];
                float v2 = acc[mt][nt][2] + add[(size_t)row2 * N + col];
                float v3 = acc[mt][nt][3] + add[(size_t)row2 * N + col + 1];
                float q0 = __shfl_xor_sync(0xffffffffu, v0, 1);
                float q1 = __shfl_xor_sync(0xffffffffu, v1, 1);
                float q2 = __shfl_xor_sync(0xffffffffu, v2, 1);
                float q3 = __shfl_xor_sync(0xffffffffu, v3, 1);
                float gi = even ? v0 : q2;
                float gf = even ? v1 : q3;
                float gg = even ? q0 : v2;
                float go = even ? q1 : v3;
                const int rr = even ? row : row2;
                const int jj = (n0 + wn * 32 + nt * 8 + ((t & 2) << 1)) >> 2;
                float si = sigf(gi), sf = sigf(gf), so = sigf(go);
                float tg = tanh_fast(gg);
                const size_t ci = (size_t)rr * H_SZ + jj;
                float cn = sf * cst[ci] + si * tg;
                cst[ci] = cn;
                float hn = so * tanh_fast(cn);
                uint16_t hh, hl;
                bsplit1(hn, hh, hl);
                h_hi[ci] = hh;
                h_lo[ci] = hl;
                outp[(size_t)rr * T_STEPS * H_SZ + (size_t)tstep * H_SZ + jj] = hn;
            }
        }
    }
}

// ---------------- prep: gate-permute + bf16 split weights ------------------
// Wp[jj*4+G, :] = split(W[G*H+jj, :])
__global__ void permute_w_split(const float* __restrict__ W,
                                uint16_t* __restrict__ Whi,
                                uint16_t* __restrict__ Wlo, int K)
{
    const int rr = blockIdx.x;          // permuted row
    const int jj = rr >> 2, G = rr & 3;
    const float4* s = (const float4*)(W + (size_t)(G * H_SZ + jj) * K);
    uint2* dh_ = (uint2*)(Whi + (size_t)rr * K);
    uint2* dl_ = (uint2*)(Wlo + (size_t)rr * K);
    for (int k = threadIdx.x; k < K / 4; k += blockDim.x) {
        float4 v = s[k];
        uint2 h, l;
        bsplit2(v.x, v.y, h.x, l.x);
        bsplit2(v.z, v.w, h.y, l.y);
        dh_[k] = h; dl_[k] = l;
    }
}

__global__ void permute_bias(const float* __restrict__ b_ih,
                             const float* __restrict__ b_hh,
                             float* __restrict__ bp)
{
    int rr = blockIdx.x * blockDim.x + threadIdx.x;
    int jj = rr >> 2, G = rr & 3;
    bp[rr] = b_ih[G * H_SZ + jj] + b_hh[G * H_SZ + jj];
}

// ---------------- split dh[1:] into bf16 planes -----------------------------
__global__ void split_dh(const float* __restrict__ src,
                         uint16_t* __restrict__ dhi, uint16_t* __restrict__ dlo)
{
    size_t i = (size_t)blockIdx.x * blockDim.x + threadIdx.x;   // over N/4
    float4 v = ((const float4*)src)[i];
    uint2 h, l;
    bsplit2(v.x, v.y, h.x, l.x);
    bsplit2(v.z, v.w, h.y, l.y);
    ((uint2*)dhi)[i] = h;
    ((uint2*)dlo)[i] = l;
}

// ---------------- pooled mean -> bf16 planes --------------------------------
__global__ void pooled_kernel(const float* __restrict__ dh,
                              const int* __restrict__ cap,
                              uint16_t* __restrict__ phi, uint16_t* __restrict__ plo)
{
    int b  = blockIdx.x;
    int d4 = threadIdx.x;                       // 256 threads, 4 elems each
    float4 acc = make_float4(0.f, 0.f, 0.f, 0.f);
    float len = 0.f;
    #pragma unroll
    for (int t = 0; t < T_STEPS; t++) {
        int v = cap[t * B_SZ + b];
        float m = (v != 0 && v != 2) ? 1.f : 0.f;
        len += m;
        float4 x = *(const float4*)(dh + (size_t)t * B_SZ * D_SZ + (size_t)b * D_SZ + d4 * 4);
        acc.x += m * x.x; acc.y += m * x.y; acc.z += m * x.z; acc.w += m * x.w;
    }
    float inv = 1.f / len;
    uint2 h, l;
    bsplit2(acc.x * inv, acc.y * inv, h.x, l.x);
    bsplit2(acc.z * inv, acc.w * inv, h.y, l.y);
    ((uint2*)(phi + (size_t)b * D_SZ))[d4] = h;
    ((uint2*)(plo + (size_t)b * D_SZ))[d4] = l;
}

// ---------------- zero c, out[:, 0, :] --------------------------------------
__global__ void init_kernel(float* __restrict__ c, float* __restrict__ out)
{
    int idx = blockIdx.x * blockDim.x + threadIdx.x;
    c[idx] = 0.f;
    int b = idx >> 10;
    int j = idx & 1023;
    out[(size_t)b * T_STEPS * H_SZ + j] = 0.f;
}

// ---------------- t=1 special step: h0=0, c0=0 ------------------------------
__global__ void lstm_step1(const float* __restrict__ gin0,
                           float* __restrict__ c,
                           uint16_t* __restrict__ h_hi, uint16_t* __restrict__ h_lo,
                           float* __restrict__ out)
{
    int idx = blockIdx.x * blockDim.x + threadIdx.x;   // over B*H
    int b = idx >> 10;
    int jj = idx & 1023;
    float4 gq = *(const float4*)(gin0 + (size_t)b * G4 + jj * 4);  // i,f,g,o
    float si = sigf(gq.x), so = sigf(gq.w);
    float cn = si * tanh_fast(gq.z);
    c[idx] = cn;
    float hn = so * tanh_fast(cn);
    uint16_t hh, hl;
    bsplit1(hn, hh, hl);
    h_hi[idx] = hh;
    h_lo[idx] = hl;
    out[(size_t)b * T_STEPS * H_SZ + (size_t)H_SZ + jj] = hn;   // t=1
}

// ---------------------------------------------------------------------------
extern "C" void kernel_launch(void* const* d_in, const int* in_sizes, int n_in,
                              void* d_out, int out_size)
{
    const float* dh    = (const float*)d_in[0];      // [T,1,B,D] == [T,B,D]
    const int*   cap   = (const int*)d_in[2];        // [T,B] int32
    const float* W_ih  = (const float*)d_in[3];      // [4H, 2D]
    const float* W_hh  = (const float*)d_in[4];      // [4H, H]
    const float* b_ih  = (const float*)d_in[5];      // [4H]
    const float* b_hh  = (const float*)d_in[6];      // [4H]
    float*       out   = (float*)d_out;              // [B, T, H]

    float *Gpool, *Gin, *c, *biasp;
    uint16_t *wih_hi, *wih_lo, *whh_hi, *whh_lo, *dh_hi, *dh_lo, *pl_hi, *pl_lo, *h_hi, *h_lo;
    cudaGetSymbolAddress((void**)&Gpool,  g_Gpool);
    cudaGetSymbolAddress((void**)&Gin,    g_Gin);
    cudaGetSymbolAddress((void**)&c,      g_c);
    cudaGetSymbolAddress((void**)&biasp,  g_bias_p);
    cudaGetSymbolAddress((void**)&wih_hi, g_wih_hi);
    cudaGetSymbolAddress((void**)&wih_lo, g_wih_lo);
    cudaGetSymbolAddress((void**)&whh_hi, g_whh_hi);
    cudaGetSymbolAddress((void**)&whh_lo, g_whh_lo);
    cudaGetSymbolAddress((void**)&dh_hi,  g_dh_hi);
    cudaGetSymbolAddress((void**)&dh_lo,  g_dh_lo);
    cudaGetSymbolAddress((void**)&pl_hi,  g_pl_hi);
    cudaGetSymbolAddress((void**)&pl_lo,  g_pl_lo);
    cudaGetSymbolAddress((void**)&h_hi,   g_h_hi);
    cudaGetSymbolAddress((void**)&h_lo,   g_h_lo);

    cudaFuncSetAttribute(gemm_bf16<0>, cudaFuncAttributeMaxDynamicSharedMemorySize, SMEM_B);
    cudaFuncSetAttribute(gemm_bf16<1>, cudaFuncAttributeMaxDynamicSharedMemorySize, SMEM_B);

    // 0) prep: permute+split weights, bias; split dh[1:]; pooled mean+split
    permute_w_split<<<G4, 256>>>(W_ih, wih_hi, wih_lo, 2 * D_SZ);
    permute_w_split<<<G4, 256>>>(W_hh, whh_hi, whh_lo, H_SZ);
    permute_bias<<<G4 / 256, 256>>>(b_ih, b_hh, biasp);
    split_dh<<<((T_STEPS - 1) * B_SZ * D_SZ / 4) / 256, 256>>>(
        dh + (size_t)B_SZ * D_SZ, dh_hi, dh_lo);
    pooled_kernel<<<B_SZ, 256>>>(dh, cap, pl_hi, pl_lo);
    init_kernel<<<(B_SZ * H_SZ) / 256, 256>>>(c, out);

    // 1) Gpool = pooled @ Wihp[:, D:]^T + bias_p
    gemm_bf16<0><<<dim3(G4 / 128, B_SZ / 128), 256, SMEM_B>>>(
        pl_hi, pl_lo, D_SZ, wih_hi + D_SZ, wih_lo + D_SZ, 2 * D_SZ,
        nullptr, 0, biasp, Gpool, G4, D_SZ,
        nullptr, nullptr, nullptr, nullptr, 0);

    // 2) Gin[t-1] = dh[t] @ Wihp[:, :D]^T + Gpool   (one big parallel GEMM)
    gemm_bf16<0><<<dim3(G4 / 128, ((T_STEPS - 1) * B_SZ) / 128), 256, SMEM_B>>>(
        dh_hi, dh_lo, D_SZ, wih_hi, wih_lo, 2 * D_SZ,
        Gpool, B_SZ, nullptr, Gin, G4, D_SZ,
        nullptr, nullptr, nullptr, nullptr, 0);

    // 3) t=1: h0=0, c0=0 -> pointwise only
    lstm_step1<<<(B_SZ * H_SZ) / 256, 256>>>(Gin, c, h_hi + B_SZ * H_SZ,
                                             h_lo + B_SZ * H_SZ, out);

    // 4) t=2..T-1: fused  gates = h @ Whhp^T + Gin[t] -> LSTM update
    for (int t = 2; t < T_STEPS; t++) {
        const int si = (t + 1) & 1, so = t & 1;
        gemm_bf16<1><<<dim3(G4 / 128, B_SZ / 128), 256, SMEM_B>>>(
            h_hi + si * (B_SZ * H_SZ), h_lo + si * (B_SZ * H_SZ), H_SZ,
            whh_hi, whh_lo, H_SZ,
            Gin + (size_t)(t - 1) * B_SZ * G4, 0, nullptr,
            nullptr, G4, H_SZ,
            c, h_hi + so * (B_SZ * H_SZ), h_lo + so * (B_SZ * H_SZ), out, t);
    }
}